// round 1
// baseline (speedup 1.0000x reference)
#include <cuda_runtime.h>
#include <cuda_bf16.h>

// Problem constants (fixed by the reference):
//   class_logits [64,300,92] f32, pred_boxes [64,300,4] f32,
//   tgt_labels [2048] i32, tgt_boxes [2048,4] f32  ->  out [64,300,2048] f32
#define BQ   19200   // 64*300
#define CC   92
#define TT   2048
#define ROWS 8       // rows (queries) per block
#define TPT  8       // targets per thread (256 threads * 8 = 2048)
#define NBLK (BQ / ROWS)   // 2400

__device__ __forceinline__ float frcp(float x) {
    float y;
    asm("rcp.approx.f32 %0, %1;" : "=f"(y) : "f"(x));
    return y;
}

__global__ __launch_bounds__(256, 2)
void matcher_kernel(const float* __restrict__ logits,
                    const float* __restrict__ pboxes,
                    const int*   __restrict__ labels,
                    const float* __restrict__ tboxes,
                    float*       __restrict__ out)
{
    __shared__ float s_prob[ROWS][CC + 4];  // padded to 96 cols
    __shared__ float s_row[ROWS][12];       // pcx,pcy,pw,ph, px0,py0,px1,py1, parea

    const int tid  = threadIdx.x;
    const int warp = tid >> 5;
    const int lane = tid & 31;
    const int row0 = blockIdx.x * ROWS;

    // ---- Phase 1: per-row softmax (warp w -> row w) + pred box derivation ----
    {
        const int rr = row0 + warp;
        const float* lrow = logits + (size_t)rr * CC;
        // lanes 0..31 cover c, c+32 always valid (92 > 63); c+64 valid for lane<28
        float l0 = lrow[lane];
        float l1 = lrow[lane + 32];
        float l2 = (lane + 64 < CC) ? lrow[lane + 64] : -1e30f;
        float m = fmaxf(l0, fmaxf(l1, l2));
        #pragma unroll
        for (int o = 16; o; o >>= 1) m = fmaxf(m, __shfl_xor_sync(0xffffffffu, m, o));
        float e0 = __expf(l0 - m);
        float e1 = __expf(l1 - m);
        float e2 = (lane + 64 < CC) ? __expf(l2 - m) : 0.0f;
        float s = e0 + e1 + e2;
        #pragma unroll
        for (int o = 16; o; o >>= 1) s += __shfl_xor_sync(0xffffffffu, s, o);
        float rinv = frcp(s);
        s_prob[warp][lane]      = e0 * rinv;
        s_prob[warp][lane + 32] = e1 * rinv;
        if (lane + 64 < CC) s_prob[warp][lane + 64] = e2 * rinv;

        if (lane == 0) {
            float4 pb = *(const float4*)(pboxes + (size_t)rr * 4);
            s_row[warp][0] = pb.x;  s_row[warp][1] = pb.y;
            s_row[warp][2] = pb.z;  s_row[warp][3] = pb.w;
            s_row[warp][4] = pb.x - 0.5f * pb.z;   // px0
            s_row[warp][5] = pb.y - 0.5f * pb.w;   // py0
            s_row[warp][6] = pb.x + 0.5f * pb.z;   // px1
            s_row[warp][7] = pb.y + 0.5f * pb.w;   // py1
            s_row[warp][8] = pb.z * pb.w;          // parea
        }
    }

    // ---- Phase 1b: this thread's 8 targets -> registers ----
    const int tbase = tid * TPT;
    float tcx[TPT], tcy[TPT], tw[TPT], th[TPT];
    float tx0[TPT], ty0[TPT], tx1[TPT], ty1[TPT], ta[TPT];
    int   lab[TPT];
    #pragma unroll
    for (int j = 0; j < TPT; j++) {
        float4 tb = *(const float4*)(tboxes + (size_t)(tbase + j) * 4);
        tcx[j] = tb.x; tcy[j] = tb.y; tw[j] = tb.z; th[j] = tb.w;
        tx0[j] = tb.x - 0.5f * tb.z;
        ty0[j] = tb.y - 0.5f * tb.w;
        tx1[j] = tb.x + 0.5f * tb.z;
        ty1[j] = tb.y + 0.5f * tb.w;
        ta[j]  = tb.z * tb.w;
        lab[j] = labels[tbase + j];
    }
    __syncthreads();

    // ---- Phase 2: 8 rows x 8 targets per thread ----
    #pragma unroll
    for (int r = 0; r < ROWS; r++) {
        const float pcx = s_row[r][0], pcy = s_row[r][1];
        const float pw  = s_row[r][2], ph  = s_row[r][3];
        const float px0 = s_row[r][4], py0 = s_row[r][5];
        const float px1 = s_row[r][6], py1 = s_row[r][7];
        const float pa  = s_row[r][8];

        float res[TPT];
        #pragma unroll
        for (int j = 0; j < TPT; j++) {
            // L1 on cxcywh
            float l1d = fabsf(pcx - tcx[j]) + fabsf(pcy - tcy[j])
                      + fabsf(pw  - tw[j])  + fabsf(ph  - th[j]);
            // intersection
            float ix0 = fmaxf(px0, tx0[j]), iy0 = fmaxf(py0, ty0[j]);
            float ix1 = fminf(px1, tx1[j]), iy1 = fminf(py1, ty1[j]);
            float iw = fmaxf(ix1 - ix0, 0.0f);
            float ih = fmaxf(iy1 - iy0, 0.0f);
            float inter = iw * ih;
            float uni   = pa + ta[j] - inter;
            // enclosing box (always well-formed; no clamp needed)
            float ex0 = fminf(px0, tx0[j]), ey0 = fminf(py0, ty0[j]);
            float ex1 = fmaxf(px1, tx1[j]), ey1 = fmaxf(py1, ty1[j]);
            float ea  = (ex1 - ex0) * (ey1 - ey0);
            float iou  = inter * frcp(uni);
            float giou = iou - (ea - uni) * frcp(ea);
            float prob = s_prob[r][lab[j]];
            // cost = 5*L1 + 1*(-prob) + 2*(-giou)
            res[j] = fmaf(5.0f, l1d, -prob) - 2.0f * giou;
        }
        float* orow = out + (size_t)(row0 + r) * TT + tbase;
        *(float4*)(orow)     = make_float4(res[0], res[1], res[2], res[3]);
        *(float4*)(orow + 4) = make_float4(res[4], res[5], res[6], res[7]);
    }
}

extern "C" void kernel_launch(void* const* d_in, const int* in_sizes, int n_in,
                              void* d_out, int out_size) {
    const float* logits = (const float*)d_in[0];   // [64,300,92]
    const float* pboxes = (const float*)d_in[1];   // [64,300,4]
    const int*   labels = (const int*)  d_in[2];   // [2048]
    const float* tboxes = (const float*)d_in[3];   // [2048,4]
    float* out = (float*)d_out;                    // [64,300,2048]
    matcher_kernel<<<NBLK, 256>>>(logits, pboxes, labels, tboxes, out);
}

// round 3
// speedup vs baseline: 1.1667x; 1.1667x over previous
#include <cuda_runtime.h>
#include <cuda_bf16.h>

// class_logits [64,300,92] f32, pred_boxes [64,300,4] f32,
// tgt_labels [2048] i32, tgt_boxes [2048,4] f32  ->  out [64,300,2048] f32
#define BQ     19200   // 64*300
#define CC     92
#define TT     2048
#define ROWS   8       // rows (queries) per block
#define TPT    4       // targets per thread
#define TBLK   1024    // targets per block (256 threads * 4)
#define GRIDX  (BQ / ROWS)   // 2400
#define GRIDY  (TT / TBLK)   // 2

__device__ __forceinline__ float frcp(float x) {
    float y;
    asm("rcp.approx.f32 %0, %1;" : "=f"(y) : "f"(x));
    return y;
}

__global__ __launch_bounds__(256, 3)
void matcher_kernel(const float* __restrict__ logits,
                    const float* __restrict__ pboxes,
                    const int*   __restrict__ labels,
                    const float* __restrict__ tboxes,
                    float*       __restrict__ out)
{
    __shared__ float s_prob[ROWS][CC + 4];  // 8 x 96
    __shared__ float s_row[ROWS][9];        // pcx,pcy,pw,ph, px0,py0,px1,py1, parea

    const int tid  = threadIdx.x;
    const int warp = tid >> 5;
    const int lane = tid & 31;
    const int row0 = blockIdx.x * ROWS;

    // ---- Phase 1: per-row softmax (warp w -> row w) + pred box derivation ----
    {
        const int rr = row0 + warp;
        const float* lrow = logits + (size_t)rr * CC;
        float l0 = lrow[lane];
        float l1 = lrow[lane + 32];
        float l2 = (lane + 64 < CC) ? lrow[lane + 64] : -1e30f;
        float m = fmaxf(l0, fmaxf(l1, l2));
        #pragma unroll
        for (int o = 16; o; o >>= 1) m = fmaxf(m, __shfl_xor_sync(0xffffffffu, m, o));
        float e0 = __expf(l0 - m);
        float e1 = __expf(l1 - m);
        float e2 = (lane + 64 < CC) ? __expf(l2 - m) : 0.0f;
        float s = e0 + e1 + e2;
        #pragma unroll
        for (int o = 16; o; o >>= 1) s += __shfl_xor_sync(0xffffffffu, s, o);
        float rinv = frcp(s);
        s_prob[warp][lane]      = e0 * rinv;
        s_prob[warp][lane + 32] = e1 * rinv;
        if (lane + 64 < CC) s_prob[warp][lane + 64] = e2 * rinv;

        if (lane == 0) {
            float4 pb = *(const float4*)(pboxes + (size_t)rr * 4);
            s_row[warp][0] = pb.x;  s_row[warp][1] = pb.y;
            s_row[warp][2] = pb.z;  s_row[warp][3] = pb.w;
            s_row[warp][4] = pb.x - 0.5f * pb.z;   // px0
            s_row[warp][5] = pb.y - 0.5f * pb.w;   // py0
            s_row[warp][6] = pb.x + 0.5f * pb.z;   // px1
            s_row[warp][7] = pb.y + 0.5f * pb.w;   // py1
            s_row[warp][8] = pb.z * pb.w;          // parea
        }
    }

    // ---- Phase 1b: this thread's 4 targets -> registers ----
    const int tbase = blockIdx.y * TBLK + tid * TPT;
    float tcx[TPT], tcy[TPT], tw[TPT], th[TPT];
    float tx0[TPT], ty0[TPT], tx1[TPT], ty1[TPT], ta[TPT];
    int lab4[TPT];
    {
        int4 lv = *(const int4*)(labels + tbase);
        lab4[0] = lv.x; lab4[1] = lv.y; lab4[2] = lv.z; lab4[3] = lv.w;
    }
    #pragma unroll
    for (int j = 0; j < TPT; j++) {
        float4 tb = *(const float4*)(tboxes + (size_t)(tbase + j) * 4);
        tcx[j] = tb.x; tcy[j] = tb.y; tw[j] = tb.z; th[j] = tb.w;
        tx0[j] = tb.x - 0.5f * tb.z;
        ty0[j] = tb.y - 0.5f * tb.w;
        tx1[j] = tb.x + 0.5f * tb.z;
        ty1[j] = tb.y + 0.5f * tb.w;
        ta[j]  = tb.z * tb.w;
    }
    __syncthreads();

    // ---- Phase 2: 8 rows x 4 targets per thread ----
    #pragma unroll
    for (int r = 0; r < ROWS; r++) {
        const float pcx = s_row[r][0], pcy = s_row[r][1];
        const float pw  = s_row[r][2], ph  = s_row[r][3];
        const float px0 = s_row[r][4], py0 = s_row[r][5];
        const float px1 = s_row[r][6], py1 = s_row[r][7];
        const float pa  = s_row[r][8];

        // prefetch class probs for this row (scalar gathers)
        float pr[TPT];
        #pragma unroll
        for (int j = 0; j < TPT; j++) pr[j] = s_prob[r][lab4[j]];

        float res[TPT];
        #pragma unroll
        for (int j = 0; j < TPT; j++) {
            // L1 on cxcywh
            float l1d = fabsf(pcx - tcx[j]) + fabsf(pcy - tcy[j])
                      + fabsf(pw  - tw[j])  + fabsf(ph  - th[j]);
            // enclosing box first; intersection via min+max identity:
            //   iw_raw = (pw + tw) - ew
            float ex0 = fminf(px0, tx0[j]), ey0 = fminf(py0, ty0[j]);
            float ex1 = fmaxf(px1, tx1[j]), ey1 = fmaxf(py1, ty1[j]);
            float ew = ex1 - ex0;
            float eh = ey1 - ey0;
            float iw = fmaxf((pw + tw[j]) - ew, 0.0f);
            float ih = fmaxf((ph + th[j]) - eh, 0.0f);
            float inter = iw * ih;
            float ea    = ew * eh;
            float uni   = (pa + ta[j]) - inter;
            float iou   = inter * frcp(uni);
            float giou  = iou - (ea - uni) * frcp(ea);
            // cost = 5*L1 - prob - 2*giou
            res[j] = fmaf(-2.0f, giou, fmaf(5.0f, l1d, -pr[j]));
        }
        float* orow = out + (size_t)(row0 + r) * TT + tbase;
        *(float4*)(orow) = make_float4(res[0], res[1], res[2], res[3]);
    }
}

extern "C" void kernel_launch(void* const* d_in, const int* in_sizes, int n_in,
                              void* d_out, int out_size) {
    const float* logits = (const float*)d_in[0];
    const float* pboxes = (const float*)d_in[1];
    const int*   labels = (const int*)  d_in[2];
    const float* tboxes = (const float*)d_in[3];
    float* out = (float*)d_out;
    matcher_kernel<<<dim3(GRIDX, GRIDY), 256>>>(logits, pboxes, labels, tboxes, out);
}

// round 4
// speedup vs baseline: 1.2005x; 1.0290x over previous
#include <cuda_runtime.h>
#include <cuda_bf16.h>

// class_logits [64,300,92] f32, pred_boxes [64,300,4] f32,
// tgt_labels [2048] i32, tgt_boxes [2048,4] f32  ->  out [64,300,2048] f32
#define BQ     19200   // 64*300
#define CC     92
#define PSTRIDE 96     // padded prob row stride (floats)
#define TT     2048
#define ROWS   8       // rows (queries) per block
#define TPT    4       // targets per thread
#define TBLK   1024    // targets per block (256 threads * 4)
#define GRIDX  (BQ / ROWS)   // 2400
#define GRIDY  (TT / TBLK)   // 2

__device__ __forceinline__ float frcp(float x) {
    float y;
    asm("rcp.approx.f32 %0, %1;" : "=f"(y) : "f"(x));
    return y;
}

__global__ __launch_bounds__(256, 3)
void matcher_kernel(const float* __restrict__ logits,
                    const float* __restrict__ pboxes,
                    const int*   __restrict__ labels,
                    const float* __restrict__ tboxes,
                    float*       __restrict__ out)
{
    __shared__ float  s_prob[ROWS][PSTRIDE]; // 8 x 96
    __shared__ float4 s_xy[ROWS];            // px0,py0,px1,py1
    __shared__ float4 s_cw[ROWS];            // pcx,pcy,pw,ph

    const int tid  = threadIdx.x;
    const int warp = tid >> 5;
    const int lane = tid & 31;
    const int row0 = blockIdx.x * ROWS;

    // ---- Phase 1: per-row softmax (warp w -> row w) + pred box derivation ----
    {
        const int rr = row0 + warp;
        const float* lrow = logits + (size_t)rr * CC;
        float l0 = lrow[lane];
        float l1 = lrow[lane + 32];
        float l2 = (lane + 64 < CC) ? lrow[lane + 64] : -1e30f;
        float m = fmaxf(l0, fmaxf(l1, l2));
        #pragma unroll
        for (int o = 16; o; o >>= 1) m = fmaxf(m, __shfl_xor_sync(0xffffffffu, m, o));
        float e0 = __expf(l0 - m);
        float e1 = __expf(l1 - m);
        float e2 = (lane + 64 < CC) ? __expf(l2 - m) : 0.0f;
        float s = e0 + e1 + e2;
        #pragma unroll
        for (int o = 16; o; o >>= 1) s += __shfl_xor_sync(0xffffffffu, s, o);
        float rinv = frcp(s);
        s_prob[warp][lane]      = e0 * rinv;
        s_prob[warp][lane + 32] = e1 * rinv;
        if (lane + 64 < CC) s_prob[warp][lane + 64] = e2 * rinv;

        if (lane == 0) {
            float4 pb = *(const float4*)(pboxes + (size_t)rr * 4);
            s_cw[warp] = pb;
            s_xy[warp] = make_float4(pb.x - 0.5f * pb.z, pb.y - 0.5f * pb.w,
                                     pb.x + 0.5f * pb.z, pb.y + 0.5f * pb.w);
        }
    }

    // ---- Phase 1b: this thread's 4 targets -> registers ----
    const int tbase = blockIdx.y * TBLK + tid * TPT;
    float tcx[TPT], tcy[TPT], tw[TPT], th[TPT];
    float tx0[TPT], ty0[TPT], tx1[TPT], ty1[TPT], ta[TPT];
    int lb[TPT];   // byte offsets into a prob row
    {
        int4 lv = *(const int4*)(labels + tbase);
        lb[0] = lv.x * 4; lb[1] = lv.y * 4; lb[2] = lv.z * 4; lb[3] = lv.w * 4;
    }
    #pragma unroll
    for (int j = 0; j < TPT; j++) {
        float4 tb = *(const float4*)(tboxes + (size_t)(tbase + j) * 4);
        tcx[j] = tb.x; tcy[j] = tb.y; tw[j] = tb.z; th[j] = tb.w;
        tx0[j] = tb.x - 0.5f * tb.z;
        ty0[j] = tb.y - 0.5f * tb.w;
        tx1[j] = tb.x + 0.5f * tb.z;
        ty1[j] = tb.y + 0.5f * tb.w;
        ta[j]  = tb.z * tb.w;
    }
    __syncthreads();

    // ---- Phase 2: 8 rows x 4 targets per thread ----
    const char* prow = (const char*)&s_prob[0][0];
    float* orow = out + (size_t)row0 * TT + tbase;
    #pragma unroll
    for (int r = 0; r < ROWS; r++) {
        const float4 xy = s_xy[r];          // one LDS.128 broadcast
        const float4 cw = s_cw[r];          // one LDS.128 broadcast
        const float px0 = xy.x, py0 = xy.y, px1 = xy.z, py1 = xy.w;
        const float pcx = cw.x, pcy = cw.y, pw = cw.z, ph = cw.w;
        const float pa  = pw * ph;

        // prob gathers: base pointer strength-reduced, labels pre-scaled
        float pr[TPT];
        #pragma unroll
        for (int j = 0; j < TPT; j++)
            pr[j] = *(const float*)(prow + lb[j]);

        float res[TPT];
        #pragma unroll
        for (int j = 0; j < TPT; j++) {
            // L1 on cxcywh
            float l1d = fabsf(pcx - tcx[j]) + fabsf(pcy - tcy[j])
                      + fabsf(pw  - tw[j])  + fabsf(ph  - th[j]);
            // enclosing box; intersection via min+max identity: iw = (pw+tw) - ew
            float ex0 = fminf(px0, tx0[j]), ey0 = fminf(py0, ty0[j]);
            float ex1 = fmaxf(px1, tx1[j]), ey1 = fmaxf(py1, ty1[j]);
            float ew = ex1 - ex0;
            float eh = ey1 - ey0;
            float iw = fmaxf((pw + tw[j]) - ew, 0.0f);
            float ih = fmaxf((ph + th[j]) - eh, 0.0f);
            float inter = iw * ih;
            float ea    = ew * eh;
            float uni   = (pa + ta[j]) - inter;
            float iou   = inter * frcp(uni);
            float giou  = iou - (ea - uni) * frcp(ea);
            // cost = 5*L1 - prob - 2*giou
            res[j] = fmaf(-2.0f, giou, fmaf(5.0f, l1d, -pr[j]));
        }
        __stcs((float4*)orow, make_float4(res[0], res[1], res[2], res[3]));
        orow += TT;
        prow += PSTRIDE * sizeof(float);
    }
}

extern "C" void kernel_launch(void* const* d_in, const int* in_sizes, int n_in,
                              void* d_out, int out_size) {
    const float* logits = (const float*)d_in[0];
    const float* pboxes = (const float*)d_in[1];
    const int*   labels = (const int*)  d_in[2];
    const float* tboxes = (const float*)d_in[3];
    float* out = (float*)d_out;
    matcher_kernel<<<dim3(GRIDX, GRIDY), 256>>>(logits, pboxes, labels, tboxes, out);
}